// round 13
// baseline (speedup 1.0000x reference)
#include <cuda_runtime.h>
#include <cstdint>

// Problem constants (fixed by reference)
#define BB      4
#define HW      400
#define OUTD    100
#define STRIDEV 4
#define NPTS    10000            // OUTD*OUTD

// Spatial grid
#define NC      64               // cells per axis
#define NCELL   (NC*NC*NC)       // 262144
#define HCELL   0.15625f         // 10.0 / 64
#define INVH    6.4f             // 1 / HCELL
#define GLO     (-5.0f)          // grid lower bound
#define CAP     16               // points per cell (overflow -> spill list)
#define OVCAP   1024             // spill list capacity per batch

// Scratch (device globals; no allocation allowed)
__device__ float4 g_t4[BB * NPTS];                    // (x, y, z, |t|^2)
__device__ int    g_cnt[BB * NCELL];                  // per-cell counts (4 MB)
__device__ float4 g_pts[(size_t)BB * NCELL * CAP];    // binned sources (256 MB)
__device__ float4 g_ovf[BB * OVCAP];                  // overflow points
__device__ int    g_ovfcnt[BB];
__device__ float  g_min[BB * NPTS];                   // min (|s|^2 - 2 t.s)

// ---------------------------------------------------------------------------
// Phase -1: clear counts (graph replays must start clean).
// grid = 256, block = 1024 -> 262144 int4 stores over g_cnt, + ovf counts.
// ---------------------------------------------------------------------------
__global__ void clear_kernel() {
    int i = blockIdx.x * blockDim.x + threadIdx.x;
    ((int4*)g_cnt)[i] = make_int4(0, 0, 0, 0);
    if (i < BB) g_ovfcnt[i] = 0;
}

// ---------------------------------------------------------------------------
// Phase 0: downsample + pack targets, bin sources into the cell grid.
// ---------------------------------------------------------------------------
__global__ void pack_bin_kernel(const float* __restrict__ tp,
                                const float* __restrict__ sp) {
    int idx = blockIdx.x * blockDim.x + threadIdx.x;
    if (idx >= 2 * BB * NPTS) return;
    bool is_src = idx >= BB * NPTS;
    int lid = is_src ? idx - BB * NPTS : idx;
    int b = lid / NPTS;
    int n = lid - b * NPTS;
    int oh = n / OUTD;
    int ow = n - oh * OUTD;
    const float* p = is_src ? sp : tp;
    long base = (long)b * 3 * HW * HW + (long)(oh * STRIDEV) * HW + (ow * STRIDEV);
    float x = p[base];
    float y = p[base + HW * HW];
    float z = p[base + 2 * HW * HW];
    float sq = x * x + y * y + z * z;
    if (!is_src) {
        g_t4[lid] = make_float4(x, y, z, sq);
        return;
    }
    int cx = (int)floorf((x - GLO) * INVH);
    int cy = (int)floorf((y - GLO) * INVH);
    int cz = (int)floorf((z - GLO) * INVH);
    cx = min(max(cx, 0), NC - 1);
    cy = min(max(cy, 0), NC - 1);
    cz = min(max(cz, 0), NC - 1);
    int ci = (cx * NC + cy) * NC + cz;
    int cell = b * NCELL + ci;
    int slot = atomicAdd(&g_cnt[cell], 1);
    float4 v = make_float4(x, y, z, sq);
    if (slot < CAP) {
        g_pts[(size_t)cell * CAP + slot] = v;
    } else {
        int o = atomicAdd(&g_ovfcnt[b], 1);
        if (o < OVCAP) g_ovf[b * OVCAP + o] = v;
    }
}

// ---------------------------------------------------------------------------
// Phase 1: grid nearest-neighbor search. One thread per target.
// best accumulates v = |s|^2 - 2 t.s  (d^2 = v + |t|^2).
// Shell pruning: any point in Chebyshev ring r is >= (r-1)*h away.
// ---------------------------------------------------------------------------
__device__ __forceinline__ void scan_cell(int cellbase, int cx, int cy, int cz,
                                          float m2x, float m2y, float m2z,
                                          float& best) {
    int cell = cellbase + (cx * NC + cy) * NC + cz;
    int cnt = g_cnt[cell];
    if (cnt > CAP) cnt = CAP;
    const float4* __restrict__ p = g_pts + (size_t)cell * CAP;
    for (int k = 0; k < cnt; ++k) {
        float4 s = p[k];
        float v = fmaf(m2x, s.x, fmaf(m2y, s.y, fmaf(m2z, s.z, s.w)));
        best = fminf(best, v);
    }
}

__global__ void __launch_bounds__(128)
search_kernel() {
    int tid = blockIdx.x * blockDim.x + threadIdx.x;
    if (tid >= BB * NPTS) return;
    int b = tid / NPTS;
    int cellbase = b * NCELL;

    float4 t = g_t4[tid];
    float m2x = -2.0f * t.x, m2y = -2.0f * t.y, m2z = -2.0f * t.z;
    float tw = t.w;

    int cx = min(max((int)floorf((t.x - GLO) * INVH), 0), NC - 1);
    int cy = min(max((int)floorf((t.y - GLO) * INVH), 0), NC - 1);
    int cz = min(max((int)floorf((t.z - GLO) * INVH), 0), NC - 1);

    float best = 3.4e38f;

    // Rings 0+1: full 3x3x3 cube (no pruning possible).
    #pragma unroll
    for (int dz = -1; dz <= 1; ++dz) {
        int z = cz + dz; if (z < 0 || z >= NC) continue;
        #pragma unroll
        for (int dy = -1; dy <= 1; ++dy) {
            int y = cy + dy; if (y < 0 || y >= NC) continue;
            #pragma unroll
            for (int dx = -1; dx <= 1; ++dx) {
                int x = cx + dx; if (x < 0 || x >= NC) continue;
                scan_cell(cellbase, x, y, z, m2x, m2y, m2z, best);
            }
        }
    }

    // Rings r >= 2 with conservative stop bound on true d^2.
    for (int r = 2; r < NC; ++r) {
        float bd = (float)(r - 1) * HCELL;
        if (best + tw <= bd * bd) break;
        for (int dz = -r; dz <= r; ++dz) {
            int z = cz + dz; if (z < 0 || z >= NC) continue;
            bool zface = (dz == r) || (dz == -r);
            for (int dy = -r; dy <= r; ++dy) {
                int y = cy + dy; if (y < 0 || y >= NC) continue;
                bool yface = (dy == r) || (dy == -r);
                if (zface || yface) {
                    for (int dx = -r; dx <= r; ++dx) {
                        int x = cx + dx; if (x < 0 || x >= NC) continue;
                        scan_cell(cellbase, x, y, z, m2x, m2y, m2z, best);
                    }
                } else {
                    int x = cx - r;
                    if (x >= 0) scan_cell(cellbase, x, y, z, m2x, m2y, m2z, best);
                    x = cx + r;
                    if (x < NC) scan_cell(cellbase, x, y, z, m2x, m2y, m2z, best);
                }
            }
        }
    }

    // Overflow spill list (normally empty).
    int oc = g_ovfcnt[b];
    if (oc > OVCAP) oc = OVCAP;
    for (int i = 0; i < oc; ++i) {
        float4 s = g_ovf[b * OVCAP + i];
        float v = fmaf(m2x, s.x, fmaf(m2y, s.y, fmaf(m2z, s.z, s.w)));
        best = fminf(best, v);
    }

    g_min[tid] = best;
}

// ---------------------------------------------------------------------------
// Phase 2: add |t|^2, deterministic tree reduce, final scale.
// Single global sum == mean of per-batch means (equal batch sizes).
// ---------------------------------------------------------------------------
__global__ void reduce_final_kernel(float* __restrict__ out) {
    __shared__ float ssum[512];
    float acc = 0.0f;
    for (int i = threadIdx.x; i < BB * NPTS; i += 512)
        acc += g_min[i] + g_t4[i].w;
    ssum[threadIdx.x] = acc;
    __syncthreads();
    for (int ofs = 256; ofs > 0; ofs >>= 1) {
        if (threadIdx.x < ofs) ssum[threadIdx.x] += ssum[threadIdx.x + ofs];
        __syncthreads();
    }
    if (threadIdx.x == 0)
        out[0] = ssum[0] * (1.0f / (float)(BB * NPTS * 3));
}

extern "C" void kernel_launch(void* const* d_in, const int* in_sizes, int n_in,
                              void* d_out, int out_size) {
    const float* tp = (const float*)d_in[0];
    const float* sp = (const float*)d_in[1];
    float* out = (float*)d_out;

    clear_kernel<<<(BB * NCELL / 4 + 1023) / 1024, 1024>>>();

    int pack_threads = 2 * BB * NPTS;
    pack_bin_kernel<<<(pack_threads + 255) / 256, 256>>>(tp, sp);

    search_kernel<<<(BB * NPTS + 127) / 128, 128>>>();

    reduce_final_kernel<<<1, 512>>>(out);
}

// round 14
// speedup vs baseline: 1.8778x; 1.8778x over previous
#include <cuda_runtime.h>
#include <cstdint>

// Problem constants (fixed by reference)
#define BB      4
#define HW      400
#define OUTD    100
#define STRIDEV 4
#define NPTS    10000            // OUTD*OUTD

// 1D z-bucket structure
#define NB      512              // buckets along z
#define ZLO     (-6.0f)
#define WZ      (12.0f / 512.0f)      // 0.0234375
#define INVW    (512.0f / 12.0f)
#define CAP     256              // slots per bucket (center mean ~94, 10 sigma margin)

// Scratch (device globals; no allocation allowed). Statically zero-initialized,
// and g_cnt is re-cleared at the end of every execution (in reduce_final).
__device__ float4 g_t4[BB * NPTS];                 // (x, y, z, |t|^2)
__device__ int    g_cnt[BB * NB];                  // per-bucket counts (8 KB)
__device__ float4 g_src[(size_t)BB * NB * CAP];    // bucketed sources (8.4 MB)
__device__ float  g_min[BB * NPTS];                // min (|s|^2 - 2 t.s)

// ---------------------------------------------------------------------------
// Phase 0: downsample + pack targets, z-bucket sources.
// ---------------------------------------------------------------------------
__global__ void pack_bin_kernel(const float* __restrict__ tp,
                                const float* __restrict__ sp) {
    int idx = blockIdx.x * blockDim.x + threadIdx.x;
    if (idx >= 2 * BB * NPTS) return;
    bool is_src = idx >= BB * NPTS;
    int lid = is_src ? idx - BB * NPTS : idx;
    int b = lid / NPTS;
    int n = lid - b * NPTS;
    int oh = n / OUTD;
    int ow = n - oh * OUTD;
    const float* p = is_src ? sp : tp;
    long base = (long)b * 3 * HW * HW + (long)(oh * STRIDEV) * HW + (ow * STRIDEV);
    float x = p[base];
    float y = p[base + HW * HW];
    float z = p[base + 2 * HW * HW];
    float sq = x * x + y * y + z * z;
    if (!is_src) {
        g_t4[lid] = make_float4(x, y, z, sq);
        return;
    }
    int q = (int)floorf((z - ZLO) * INVW);
    q = min(max(q, 0), NB - 1);
    int cell = b * NB + q;
    int slot = atomicAdd(&g_cnt[cell], 1);
    if (slot < CAP)
        g_src[(size_t)cell * CAP + slot] = make_float4(x, y, z, sq);
}

// ---------------------------------------------------------------------------
// Phase 1: exact NN via outward z-bucket scan. 2 lanes per target:
// lane side==0 scans decreasing z, side==1 increasing z; both seed on the
// home bucket; results merged with shfl. best accumulates |s|^2 - 2 t.s
// so d^2 = best + |t|^2; stop a side when dz_bound^2 >= best + |t|^2.
// ---------------------------------------------------------------------------
__device__ __forceinline__ void scan_bucket(int cell, float m2x, float m2y,
                                            float m2z, float& best) {
    int cnt = g_cnt[cell];
    if (cnt > CAP) cnt = CAP;
    const float4* __restrict__ p = g_src + (size_t)cell * CAP;
    int k = 0;
    for (; k + 4 <= cnt; k += 4) {
        float4 s0 = p[k], s1 = p[k + 1], s2 = p[k + 2], s3 = p[k + 3];
        float v0 = fmaf(m2x, s0.x, fmaf(m2y, s0.y, fmaf(m2z, s0.z, s0.w)));
        float v1 = fmaf(m2x, s1.x, fmaf(m2y, s1.y, fmaf(m2z, s1.z, s1.w)));
        float v2 = fmaf(m2x, s2.x, fmaf(m2y, s2.y, fmaf(m2z, s2.z, s2.w)));
        float v3 = fmaf(m2x, s3.x, fmaf(m2y, s3.y, fmaf(m2z, s3.z, s3.w)));
        best = fminf(best, fminf(fminf(v0, v1), fminf(v2, v3)));
    }
    for (; k < cnt; ++k) {
        float4 s = p[k];
        float v = fmaf(m2x, s.x, fmaf(m2y, s.y, fmaf(m2z, s.z, s.w)));
        best = fminf(best, v);
    }
}

__global__ void __launch_bounds__(128)
search_kernel() {
    int lane2 = blockIdx.x * blockDim.x + threadIdx.x;   // 0 .. 2*BB*NPTS-1
    int tgt  = lane2 >> 1;
    int side = lane2 & 1;
    int b = tgt / NPTS;

    float4 t = g_t4[tgt];
    float m2x = -2.0f * t.x, m2y = -2.0f * t.y, m2z = -2.0f * t.z;
    float tw = t.w;

    int q0 = min(max((int)floorf((t.z - ZLO) * INVW), 0), NB - 1);
    int cellbase = b * NB;

    float best = 3.4e38f;
    scan_bucket(cellbase + q0, m2x, m2y, m2z, best);

    if (side == 0) {
        for (int q = q0 - 1; q >= 0; --q) {
            float dz = t.z - (ZLO + (float)(q + 1) * WZ);   // >= 0
            if (dz * dz >= best + tw) break;
            scan_bucket(cellbase + q, m2x, m2y, m2z, best);
        }
    } else {
        for (int q = q0 + 1; q < NB; ++q) {
            float dz = (ZLO + (float)q * WZ) - t.z;          // >= 0
            if (dz * dz >= best + tw) break;
            scan_bucket(cellbase + q, m2x, m2y, m2z, best);
        }
    }

    best = fminf(best, __shfl_xor_sync(0xFFFFFFFFu, best, 1));
    if (side == 0) g_min[tgt] = best;
}

// ---------------------------------------------------------------------------
// Phase 2: add |t|^2, deterministic tree reduce, final scale. Also clears
// the bucket counts so the next graph replay starts clean.
// Single global sum == mean of per-batch means (equal batch sizes).
// ---------------------------------------------------------------------------
__global__ void reduce_final_kernel(float* __restrict__ out) {
    __shared__ float ssum[1024];
    // Clear bucket counts for the next execution (different array than g_min).
    for (int i = threadIdx.x; i < BB * NB; i += 1024)
        g_cnt[i] = 0;
    float acc = 0.0f;
    for (int i = threadIdx.x; i < BB * NPTS; i += 1024)
        acc += g_min[i] + g_t4[i].w;
    ssum[threadIdx.x] = acc;
    __syncthreads();
    for (int ofs = 512; ofs > 0; ofs >>= 1) {
        if (threadIdx.x < ofs) ssum[threadIdx.x] += ssum[threadIdx.x + ofs];
        __syncthreads();
    }
    if (threadIdx.x == 0)
        out[0] = ssum[0] * (1.0f / (float)(BB * NPTS * 3));
}

extern "C" void kernel_launch(void* const* d_in, const int* in_sizes, int n_in,
                              void* d_out, int out_size) {
    const float* tp = (const float*)d_in[0];
    const float* sp = (const float*)d_in[1];
    float* out = (float*)d_out;

    int pack_threads = 2 * BB * NPTS;
    pack_bin_kernel<<<(pack_threads + 255) / 256, 256>>>(tp, sp);

    int search_lanes = 2 * BB * NPTS;                    // 80000
    search_kernel<<<(search_lanes + 127) / 128, 128>>>();

    reduce_final_kernel<<<1, 1024>>>(out);
}